// round 3
// baseline (speedup 1.0000x reference)
#include <cuda_runtime.h>
#include <math.h>

#define BB   128
#define NNOD 50
#define SEQ  51
#define DIM  128
#define NH   8
#define DHE  16
#define FFD  512
#define NLE  6
#define NLD  2
#define GRP  4                   // batch elements per decoder block
#define MTOT (BB*SEQ)            // 6528
#define SZ_MD (MTOT*DIM)         // 835584

// ---------------- scratch ----------------
#define OFF_T    (SZ_MD)
#define OFF_Q    (2*SZ_MD)
#define OFF_K    (3*SZ_MD)
#define OFF_V    (4*SZ_MD)
#define OFF_O    (5*SZ_MD)
#define OFF_F    (6*SZ_MD)
#define OFF_KATT (10*SZ_MD)
#define OFF_VATT (12*SZ_MD)
#define OFF_KFIN (14*SZ_MD)
#define OFF_PART (15*SZ_MD)
#define OFF_MEAN (OFF_PART + 16384)
#define OFF_RSTD (OFF_MEAN + 128)
#define OFF_PE   (OFF_RSTD + 128)
#define OFF_KC   (OFF_PE + NNOD*DIM)
#define SZ_KC    (NLD*BB*NH*NNOD*DHE)
#define OFF_VC   (OFF_KC + SZ_KC)
#define SCRATCH_TOTAL (OFF_VC + SZ_KC)

__device__ float g_scratch[SCRATCH_TOTAL];

// ---------------- embedding ----------------
__global__ void embed_kernel(const float* __restrict__ x,
                             const float* __restrict__ w_in,
                             const float* __restrict__ b_in,
                             const float* __restrict__ start_ph,
                             float* __restrict__ h)
{
    int i = blockIdx.x * blockDim.x + threadIdx.x;
    if (i >= MTOT * DIM) return;
    int d = i & 127;
    int row = i >> 7;
    int s = row % SEQ;
    int b = row / SEQ;
    float v;
    if (s < NNOD) {
        const float* xp = x + (b * NNOD + s) * 2;
        v = xp[0] * w_in[d] + xp[1] * w_in[DIM + d] + b_in[d];
    } else {
        v = start_ph[d];
    }
    h[i] = v;
}

// ---------------- positional encoding ----------------
__global__ void pe_kernel(float* __restrict__ pe)
{
    int i = blockIdx.x * blockDim.x + threadIdx.x;
    if (i >= NNOD * DIM) return;
    int t = i >> 7, d = i & 127;
    double e = (double)(2 * (d / 2)) / 128.0;
    double ang = (double)t * pow(10000.0, -e);
    pe[i] = (float)(((d & 1) == 0) ? sin(ang) : cos(ang));
}

// ---------------- SGEMM: C = A[M,K] @ W[K,N] (+bias)(relu)(+res) ----------------
// ZSTRIDE: if true, blockIdx.z selects weight/bias/output slab (fused QKV)
template<bool BIAS, bool RELU, bool RES, bool ZSTRIDE>
__global__ void __launch_bounds__(256) sgemm(const float* __restrict__ A,
                                             const float* __restrict__ W,
                                             const float* __restrict__ bias,
                                             const float* __restrict__ R,
                                             float* __restrict__ C,
                                             int M, int N, int K)
{
    if (ZSTRIDE) {
        int z = blockIdx.z;
        W += (size_t)z * K * N;
        if (BIAS) bias += (size_t)z * N;
        C += (size_t)z * M * N;
    }
    __shared__ float As[16][68];
    __shared__ float Bs[16][68];
    int bm = blockIdx.y * 64, bn = blockIdx.x * 64;
    int tid = threadIdx.x;
    int tr = tid >> 4, tc = tid & 15;
    float acc[4][4] = {};
    for (int k0 = 0; k0 < K; k0 += 16) {
        int m = tid >> 2, kk = (tid & 3) * 4;
        float4 av = *(const float4*)&A[(bm + m) * K + k0 + kk];
        As[kk + 0][m] = av.x; As[kk + 1][m] = av.y;
        As[kk + 2][m] = av.z; As[kk + 3][m] = av.w;
        int kr = tid >> 4, cc = (tid & 15) * 4;
        float4 bv = *(const float4*)&W[(k0 + kr) * N + bn + cc];
        Bs[kr][cc + 0] = bv.x; Bs[kr][cc + 1] = bv.y;
        Bs[kr][cc + 2] = bv.z; Bs[kr][cc + 3] = bv.w;
        __syncthreads();
#pragma unroll
        for (int k2 = 0; k2 < 16; k2++) {
            float ra[4], rb[4];
#pragma unroll
            for (int i = 0; i < 4; i++) { ra[i] = As[k2][tr * 4 + i]; rb[i] = Bs[k2][tc * 4 + i]; }
#pragma unroll
            for (int i = 0; i < 4; i++)
#pragma unroll
                for (int j = 0; j < 4; j++) acc[i][j] += ra[i] * rb[j];
        }
        __syncthreads();
    }
#pragma unroll
    for (int i = 0; i < 4; i++) {
        int m = bm + tr * 4 + i;
#pragma unroll
        for (int j = 0; j < 4; j++) {
            int n = bn + tc * 4 + j;
            float v = acc[i][j];
            if (BIAS) v += bias[n];
            if (RELU) v = fmaxf(v, 0.f);
            if (RES)  v += R[m * N + n];
            C[m * N + n] = v;
        }
    }
}

// ---------------- encoder attention: one block per (b, head) ----------------
__global__ void __launch_bounds__(128) enc_attn(const float* __restrict__ Q,
                                                const float* __restrict__ K,
                                                const float* __restrict__ V,
                                                float* __restrict__ O)
{
    __shared__ float Qs[SEQ][DHE], Ks[SEQ][DHE], Vs[SEQ][DHE];
    __shared__ float P[SEQ][SEQ + 1];
    int bh = blockIdx.x;
    int b = bh / NH, hh = bh % NH;
    int tid = threadIdx.x;
    for (int i = tid; i < SEQ * DHE; i += 128) {
        int s = i / DHE, j = i % DHE;
        int g = (b * SEQ + s) * DIM + hh * DHE + j;
        Qs[s][j] = Q[g]; Ks[s][j] = K[g]; Vs[s][j] = V[g];
    }
    __syncthreads();
    for (int p = tid; p < SEQ * SEQ; p += 128) {
        int q = p / SEQ, k = p % SEQ;
        float s = 0.f;
#pragma unroll
        for (int j = 0; j < DHE; j++) s += Qs[q][j] * Ks[k][j];
        P[q][k] = s * 0.25f;
    }
    __syncthreads();
    if (tid < SEQ) {
        float mx = -1e30f;
        for (int k = 0; k < SEQ; k++) mx = fmaxf(mx, P[tid][k]);
        float sum = 0.f;
        for (int k = 0; k < SEQ; k++) { float e = expf(P[tid][k] - mx); P[tid][k] = e; sum += e; }
        float inv = 1.f / sum;
        for (int k = 0; k < SEQ; k++) P[tid][k] *= inv;
    }
    __syncthreads();
    for (int p = tid; p < SEQ * DHE; p += 128) {
        int q = p / DHE, j = p % DHE;
        float s = 0.f;
        for (int k = 0; k < SEQ; k++) s += P[q][k] * Vs[k][j];
        O[(b * SEQ + q) * DIM + hh * DHE + j] = s;
    }
}

// ---------------- BatchNorm (deterministic 3-stage) ----------------
__global__ void __launch_bounds__(256) bn_partial(const float* __restrict__ X,
                                                  float* __restrict__ part)
{
    int d = threadIdx.x & 127, half = threadIdx.x >> 7;
    int r0 = blockIdx.x * 102;
    float s = 0.f, ss = 0.f;
    for (int r = r0 + half; r < r0 + 102; r += 2) {
        float v = X[r * DIM + d];
        s += v; ss += v * v;
    }
    __shared__ float sh[2][2][128];
    sh[half][0][d] = s; sh[half][1][d] = ss;
    __syncthreads();
    if (!half) {
        part[blockIdx.x * 256 + d]       = s + sh[1][0][d];
        part[blockIdx.x * 256 + 128 + d] = ss + sh[1][1][d];
    }
}

__global__ void bn_reduce(const float* __restrict__ part,
                          float* __restrict__ mean, float* __restrict__ rstd)
{
    int d = threadIdx.x;
    float s = 0.f, ss = 0.f;
    for (int b = 0; b < 64; b++) { s += part[b * 256 + d]; ss += part[b * 256 + 128 + d]; }
    float m = s * (1.f / (float)MTOT);
    float v = ss * (1.f / (float)MTOT) - m * m;
    mean[d] = m;
    rstd[d] = rsqrtf(v + 1e-5f);
}

__global__ void __launch_bounds__(256) bn_apply(const float* __restrict__ X,
                                                const float* __restrict__ mean,
                                                const float* __restrict__ rstd,
                                                const float* __restrict__ gamma,
                                                const float* __restrict__ beta,
                                                float* __restrict__ Y)
{
    int i = blockIdx.x * blockDim.x + threadIdx.x;
    if (i >= MTOT * DIM) return;
    int d = i & 127;
    Y[i] = gamma[d] * (X[i] - mean[d]) * rstd[d] + beta[d];
}

// ---------------- decoder helpers (per-group reduction across 4 warps) ----------------
__device__ __forceinline__ float blksum_g(float v, float* red4)
{
#pragma unroll
    for (int o = 16; o; o >>= 1) v += __shfl_down_sync(0xffffffffu, v, o);
    int w = (threadIdx.x >> 5) & 3;
    if ((threadIdx.x & 31) == 0) red4[w] = v;
    __syncthreads();
    float r = (red4[0] + red4[1]) + (red4[2] + red4[3]);
    __syncthreads();
    return r;
}

__device__ __forceinline__ void layernorm_g(float* u, float* htg, const float* gb,
                                            int d, float* red4)
{
    float mean = blksum_g(u[d], red4) * (1.f / 128.f);
    float diff = u[d] - mean;
    float var = blksum_g(diff * diff, red4) * (1.f / 128.f);
    float rstd = rsqrtf(var + 1e-5f);
    htg[d] = gb[d] * diff * rstd + gb[DIM + d];
    __syncthreads();
}

// ---------------- persistent decoder: GRP batch elements per block ----------------
__global__ void __launch_bounds__(512) decoder_kernel(
    const float* __restrict__ h_enc, const float* __restrict__ pe,
    const float* __restrict__ Katt, const float* __restrict__ Vatt,
    const float* __restrict__ Kfin,
    float* __restrict__ Kc, float* __restrict__ Vc,
    const float* __restrict__ dsw, const float* __restrict__ dsb,
    const float* __restrict__ dcw, const float* __restrict__ dcb,
    const float* __restrict__ dw1, const float* __restrict__ db1,
    const float* __restrict__ dw2, const float* __restrict__ db2,
    const float* __restrict__ dln, const float* __restrict__ wqf,
    float* __restrict__ out)
{
    int g = threadIdx.x >> 7;            // 0..3 group within block
    int d = threadIdx.x & 127;           // output column
    int b = blockIdx.x * GRP + g;        // batch element
    int hh = d >> 4, dh = d & 15;

    __shared__ float ht[GRP][DIM], sq[GRP][DIM], so[GRP][DIM], su[GRP][DIM];
    __shared__ float sf[GRP][FFD];
    __shared__ float sc[GRP][NH][SEQ + 1];
    __shared__ float red[GRP][4];
    __shared__ float slg[GRP][SEQ];
    __shared__ int   smask[GRP][SEQ];
    __shared__ int   scur[GRP];
    __shared__ float sslp[GRP];

    float* htg = ht[g];
    float* sqg = sq[g];
    float* sog = so[g];
    float* sug = su[g];
    float* sfg = sf[g];
    float* redg = red[g];

    for (int n = d; n < SEQ; n += 128) smask[g][n] = (n == NNOD) ? 1 : 0;
    if (d == 0) { scur[g] = NNOD; sslp[g] = 0.f; }
    __syncthreads();

    for (int t = 0; t < NNOD; t++) {
        htg[d] = h_enc[(b * SEQ + scur[g]) * DIM + d] + pe[t * DIM + d];
        __syncthreads();

        for (int l = 0; l < NLD; l++) {
            // ---- self attention QKV ----
            const float* W = dsw + l * 4 * DIM * DIM;
            const float* bb = dsb + l * 4 * DIM;
            {
                float a0 = bb[d], a1 = bb[DIM + d], a2 = bb[2 * DIM + d];
#pragma unroll 16
                for (int k = 0; k < DIM; k++) {
                    float hk = htg[k];
                    a0 += hk * W[k * DIM + d];
                    a1 += hk * W[DIM * DIM + k * DIM + d];
                    a2 += hk * W[2 * DIM * DIM + k * DIM + d];
                }
                sqg[d] = a0;
                int cb = ((l * BB + b) * NH + hh) * NNOD * DHE;
                Kc[cb + t * DHE + dh] = a1;
                Vc[cb + t * DHE + dh] = a2;
            }
            __syncthreads();

            int nt = t + 1;
            for (int p = d; p < NH * nt; p += 128) {
                int ph = p / nt, ps = p % nt;
                const float* kp = &Kc[((l * BB + b) * NH + ph) * NNOD * DHE + ps * DHE];
                const float* qp = &sqg[ph * DHE];
                float s = 0.f;
#pragma unroll
                for (int j = 0; j < DHE; j++) s += qp[j] * kp[j];
                sc[g][ph][ps] = s * 0.25f;
            }
            __syncthreads();
            if (d < NH) {
                float mx = -1e30f;
                for (int s = 0; s < nt; s++) mx = fmaxf(mx, sc[g][d][s]);
                float sm = 0.f;
                for (int s = 0; s < nt; s++) { float e = expf(sc[g][d][s] - mx); sc[g][d][s] = e; sm += e; }
                float inv = 1.f / sm;
                for (int s = 0; s < nt; s++) sc[g][d][s] *= inv;
            }
            __syncthreads();
            {
                float oo = 0.f;
                const float* vp = &Vc[((l * BB + b) * NH + hh) * NNOD * DHE + dh];
                for (int s = 0; s < nt; s++) oo += sc[g][hh][s] * vp[s * DHE];
                sog[d] = oo;
            }
            __syncthreads();
            {
                const float* Wo = W + 3 * DIM * DIM;
                float a = bb[3 * DIM + d];
#pragma unroll 16
                for (int k = 0; k < DIM; k++) a += sog[k] * Wo[k * DIM + d];
                sug[d] = htg[d] + a;
            }
            __syncthreads();
            layernorm_g(sug, htg, dln + ((l * 3 + 0) * 2) * DIM, d, redg);

            // ---- cross attention ----
            const float* Wc = dcw + l * 2 * DIM * DIM;
            const float* bc = dcb + l * 2 * DIM;
            {
                float a = bc[d];
#pragma unroll 16
                for (int k = 0; k < DIM; k++) a += htg[k] * Wc[k * DIM + d];
                sqg[d] = a;
            }
            __syncthreads();
            for (int p = d; p < NH * SEQ; p += 128) {
                int ph = p / SEQ, pn = p % SEQ;
                const float* kp = &Katt[(b * SEQ + pn) * (NLD * DIM) + l * DIM + ph * DHE];
                const float* qp = &sqg[ph * DHE];
                float s = 0.f;
#pragma unroll
                for (int j = 0; j < DHE; j++) s += qp[j] * kp[j];
                sc[g][ph][pn] = s * 0.25f;
            }
            __syncthreads();
            if (d < NH) {
                float mx = -1e30f;
                for (int n = 0; n < SEQ; n++) mx = fmaxf(mx, sc[g][d][n]);
                float sm = 0.f;
                for (int n = 0; n < SEQ; n++) { float e = expf(sc[g][d][n] - mx); sc[g][d][n] = e; sm += e; }
                float inv = 1.f / sm;
                for (int n = 0; n < SEQ; n++) sc[g][d][n] *= inv;
            }
            __syncthreads();
            {
                float oo = 0.f;
                const float* vp = &Vatt[b * SEQ * (NLD * DIM) + l * DIM + d];
                for (int n = 0; n < SEQ; n++) oo += sc[g][hh][n] * vp[n * NLD * DIM];
                sog[d] = oo;
            }
            __syncthreads();
            {
                const float* W2c = Wc + DIM * DIM;
                float a = bc[DIM + d];
#pragma unroll 16
                for (int k = 0; k < DIM; k++) a += sog[k] * W2c[k * DIM + d];
                sug[d] = htg[d] + a;
            }
            __syncthreads();
            layernorm_g(sug, htg, dln + ((l * 3 + 1) * 2) * DIM, d, redg);

            // ---- FFN ----
            {
                const float* W1 = dw1 + l * DIM * FFD;
                const float* b1 = db1 + l * FFD;
                float a0 = b1[d], a1 = b1[d + 128], a2 = b1[d + 256], a3 = b1[d + 384];
#pragma unroll 8
                for (int k = 0; k < DIM; k++) {
                    float hk = htg[k];
                    const float* wr = &W1[k * FFD + d];
                    a0 += hk * wr[0];
                    a1 += hk * wr[128];
                    a2 += hk * wr[256];
                    a3 += hk * wr[384];
                }
                sfg[d]       = fmaxf(a0, 0.f);
                sfg[d + 128] = fmaxf(a1, 0.f);
                sfg[d + 256] = fmaxf(a2, 0.f);
                sfg[d + 384] = fmaxf(a3, 0.f);
            }
            __syncthreads();
            {
                const float* W2 = dw2 + l * FFD * DIM;
                float a = db2[l * DIM + d];
#pragma unroll 16
                for (int k = 0; k < FFD; k++) a += sfg[k] * W2[k * DIM + d];
                sug[d] = htg[d] + a;
            }
            __syncthreads();
            layernorm_g(sug, htg, dln + ((l * 3 + 2) * 2) * DIM, d, redg);
        }

        // ---- final pointer logits ----
        {
            float a = 0.f;
#pragma unroll 16
            for (int k = 0; k < DIM; k++) a += htg[k] * wqf[k * DIM + d];
            sqg[d] = a;
        }
        __syncthreads();
        for (int n = d; n < SEQ; n += 128) {
            const float* kp = &Kfin[(b * SEQ + n) * DIM];
            float s = 0.f;
#pragma unroll 16
            for (int k = 0; k < DIM; k++) s += sqg[k] * kp[k];
            float lg = 10.f * tanhf(s * 0.08838834764831845f);   // 1/sqrt(128)
            slg[g][n] = smask[g][n] ? -1e9f : lg;
        }
        __syncthreads();
        if (d == 0) {
            float mx = -1e30f;
            int am = 0;
            for (int n = 0; n < SEQ; n++) if (slg[g][n] > mx) { mx = slg[g][n]; am = n; }
            float sm = 0.f;
            for (int n = 0; n < SEQ; n++) sm += expf(slg[g][n] - mx);
            sslp[g] += -logf(sm);
            smask[g][am] = 1;
            scur[g] = am;
            out[b * NNOD + t] = (float)am;
        }
        __syncthreads();
    }
    if (d == 0) out[BB * NNOD + b] = sslp[g];
}

// ---------------- host launcher ----------------
extern "C" void kernel_launch(void* const* d_in, const int* in_sizes, int n_in,
                              void* d_out, int out_size)
{
    const float* x          = (const float*)d_in[0];
    const float* w_input    = (const float*)d_in[1];
    const float* b_input    = (const float*)d_in[2];
    const float* start_ph   = (const float*)d_in[3];
    const float* enc_attn_w = (const float*)d_in[4];
    const float* enc_attn_b = (const float*)d_in[5];
    const float* enc_ffn_w1 = (const float*)d_in[6];
    const float* enc_ffn_b1 = (const float*)d_in[7];
    const float* enc_ffn_w2 = (const float*)d_in[8];
    const float* enc_ffn_b2 = (const float*)d_in[9];
    const float* enc_bn     = (const float*)d_in[10];
    const float* dec_self_w = (const float*)d_in[11];
    const float* dec_self_b = (const float*)d_in[12];
    const float* dec_cross_w= (const float*)d_in[13];
    const float* dec_cross_b= (const float*)d_in[14];
    const float* dec_ffn_w1 = (const float*)d_in[15];
    const float* dec_ffn_b1 = (const float*)d_in[16];
    const float* dec_ffn_w2 = (const float*)d_in[17];
    const float* dec_ffn_b2 = (const float*)d_in[18];
    const float* dec_ln     = (const float*)d_in[19];
    const float* wk_dec     = (const float*)d_in[20];
    const float* bk_dec     = (const float*)d_in[21];
    const float* wv_dec     = (const float*)d_in[22];
    const float* bv_dec     = (const float*)d_in[23];
    const float* wq_final   = (const float*)d_in[24];
    const float* wk_final   = (const float*)d_in[25];
    float* out = (float*)d_out;

    float* base = nullptr;
    cudaGetSymbolAddress((void**)&base, g_scratch);
    float* ph    = base;
    float* pt    = base + OFF_T;
    float* pQ    = base + OFF_Q;
    float* pf    = base + OFF_F;
    float* pKatt = base + OFF_KATT;
    float* pVatt = base + OFF_VATT;
    float* pKfin = base + OFF_KFIN;
    float* ppart = base + OFF_PART;
    float* pmean = base + OFF_MEAN;
    float* prstd = base + OFF_RSTD;
    float* ppe   = base + OFF_PE;
    float* pKc   = base + OFF_KC;
    float* pVc   = base + OFF_VC;

    embed_kernel<<<(MTOT * DIM + 255) / 256, 256>>>(x, w_input, b_input, start_ph, ph);
    pe_kernel<<<(NNOD * DIM + 255) / 256, 256>>>(ppe);

    dim3 gDD(DIM / 64, MTOT / 64);            // N=128
    dim3 gQKV(DIM / 64, MTOT / 64, 3);        // fused Q,K,V
    dim3 gDF(FFD / 64, MTOT / 64);            // N=512
    dim3 gD2(256 / 64, MTOT / 64);            // N=256

    for (int l = 0; l < NLE; l++) {
        const float* aw = enc_attn_w + (size_t)l * 4 * DIM * DIM;
        const float* ab = enc_attn_b + (size_t)l * 4 * DIM;
        // fused QKV: outputs land in contiguous Q,K,V scratch slabs
        sgemm<true, false, false, true><<<gQKV, 256>>>(ph, aw, ab, nullptr, pQ, MTOT, DIM, DIM);
        enc_attn<<<BB * NH, 128>>>(pQ, pQ + SZ_MD, pQ + 2 * SZ_MD, base + OFF_O);
        sgemm<true, false, true, false><<<gDD, 256>>>(base + OFF_O, aw + 3 * DIM * DIM,
                 ab + 3 * DIM, ph, pt, MTOT, DIM, DIM);
        bn_partial<<<64, 256>>>(pt, ppart);
        bn_reduce<<<1, 128>>>(ppart, pmean, prstd);
        bn_apply<<<(MTOT * DIM + 255) / 256, 256>>>(pt, pmean, prstd,
                 enc_bn + ((l * 2 + 0) * 2 + 0) * DIM, enc_bn + ((l * 2 + 0) * 2 + 1) * DIM, ph);
        sgemm<true, true, false, false><<<gDF, 256>>>(ph, enc_ffn_w1 + (size_t)l * DIM * FFD,
                 enc_ffn_b1 + (size_t)l * FFD, nullptr, pf, MTOT, FFD, DIM);
        sgemm<true, false, true, false><<<gDD, 256>>>(pf, enc_ffn_w2 + (size_t)l * FFD * DIM,
                 enc_ffn_b2 + (size_t)l * DIM, ph, pt, MTOT, DIM, FFD);
        bn_partial<<<64, 256>>>(pt, ppart);
        bn_reduce<<<1, 128>>>(ppart, pmean, prstd);
        bn_apply<<<(MTOT * DIM + 255) / 256, 256>>>(pt, pmean, prstd,
                 enc_bn + ((l * 2 + 1) * 2 + 0) * DIM, enc_bn + ((l * 2 + 1) * 2 + 1) * DIM, ph);
    }

    // decoder cross-attn K/V and final pointer keys
    sgemm<true,  false, false, false><<<gD2, 256>>>(ph, wk_dec,   bk_dec,  nullptr, pKatt, MTOT, NLD * DIM, DIM);
    sgemm<true,  false, false, false><<<gD2, 256>>>(ph, wv_dec,   bv_dec,  nullptr, pVatt, MTOT, NLD * DIM, DIM);
    sgemm<false, false, false, false><<<gDD, 256>>>(ph, wk_final, nullptr, nullptr, pKfin, MTOT, DIM, DIM);

    decoder_kernel<<<BB / GRP, 512>>>(ph, ppe, pKatt, pVatt, pKfin, pKc, pVc,
                                dec_self_w, dec_self_b, dec_cross_w, dec_cross_b,
                                dec_ffn_w1, dec_ffn_b1, dec_ffn_w2, dec_ffn_b2,
                                dec_ln, wq_final, out);
}

// round 5
// speedup vs baseline: 2.6612x; 2.6612x over previous
#include <cuda_runtime.h>
#include <math.h>

#define BB   128
#define NNOD 50
#define SEQ  51
#define DIM  128
#define NH   8
#define DHE  16
#define FFD  512
#define NLE  6
#define NLD  2
#define MTOT (BB*SEQ)            // 6528
#define SZ_MD (MTOT*DIM)         // 835584

// ---------------- scratch ----------------
#define OFF_T    (SZ_MD)
#define OFF_Q    (2*SZ_MD)
#define OFF_O    (5*SZ_MD)
#define OFF_F    (6*SZ_MD)
#define OFF_KATT (10*SZ_MD)
#define OFF_VATT (12*SZ_MD)
#define OFF_KFIN (14*SZ_MD)
#define OFF_PART (15*SZ_MD)
#define OFF_MEAN (OFF_PART + 16384)
#define OFF_RSTD (OFF_MEAN + 128)
#define OFF_PE   (OFF_RSTD + 128)
#define OFF_KC   (OFF_PE + NNOD*DIM)
#define SZ_KC    (NLD*BB*NH*NNOD*DHE)
#define OFF_VC   (OFF_KC + SZ_KC)
#define SCRATCH_TOTAL (OFF_VC + SZ_KC)

__device__ float g_scratch[SCRATCH_TOTAL];

// ---------------- embedding ----------------
__global__ void embed_kernel(const float* __restrict__ x,
                             const float* __restrict__ w_in,
                             const float* __restrict__ b_in,
                             const float* __restrict__ start_ph,
                             float* __restrict__ h)
{
    int i = blockIdx.x * blockDim.x + threadIdx.x;
    if (i >= MTOT * DIM) return;
    int d = i & 127;
    int row = i >> 7;
    int s = row % SEQ;
    int b = row / SEQ;
    float v;
    if (s < NNOD) {
        const float* xp = x + (b * NNOD + s) * 2;
        v = xp[0] * w_in[d] + xp[1] * w_in[DIM + d] + b_in[d];
    } else {
        v = start_ph[d];
    }
    h[i] = v;
}

// ---------------- positional encoding ----------------
__global__ void pe_kernel(float* __restrict__ pe)
{
    int i = blockIdx.x * blockDim.x + threadIdx.x;
    if (i >= NNOD * DIM) return;
    int t = i >> 7, d = i & 127;
    double e = (double)(2 * (d / 2)) / 128.0;
    double ang = (double)t * pow(10000.0, -e);
    pe[i] = (float)(((d & 1) == 0) ? sin(ang) : cos(ang));
}

// ---------------- SGEMM: C = A[M,K] @ W[K,N] (+bias)(relu)(+res) ----------------
template<bool BIAS, bool RELU, bool RES, bool ZSTRIDE>
__global__ void __launch_bounds__(256) sgemm(const float* __restrict__ A,
                                             const float* __restrict__ W,
                                             const float* __restrict__ bias,
                                             const float* __restrict__ R,
                                             float* __restrict__ C,
                                             int M, int N, int K)
{
    if (ZSTRIDE) {
        int z = blockIdx.z;
        W += (size_t)z * K * N;
        if (BIAS) bias += (size_t)z * N;
        C += (size_t)z * M * N;
    }
    __shared__ float As[16][68];
    __shared__ float Bs[16][68];
    int bm = blockIdx.y * 64, bn = blockIdx.x * 64;
    int tid = threadIdx.x;
    int tr = tid >> 4, tc = tid & 15;
    float acc[4][4] = {};
    for (int k0 = 0; k0 < K; k0 += 16) {
        int m = tid >> 2, kk = (tid & 3) * 4;
        float4 av = *(const float4*)&A[(bm + m) * K + k0 + kk];
        As[kk + 0][m] = av.x; As[kk + 1][m] = av.y;
        As[kk + 2][m] = av.z; As[kk + 3][m] = av.w;
        int kr = tid >> 4, cc = (tid & 15) * 4;
        float4 bv = *(const float4*)&W[(k0 + kr) * N + bn + cc];
        Bs[kr][cc + 0] = bv.x; Bs[kr][cc + 1] = bv.y;
        Bs[kr][cc + 2] = bv.z; Bs[kr][cc + 3] = bv.w;
        __syncthreads();
#pragma unroll
        for (int k2 = 0; k2 < 16; k2++) {
            float ra[4], rb[4];
#pragma unroll
            for (int i = 0; i < 4; i++) { ra[i] = As[k2][tr * 4 + i]; rb[i] = Bs[k2][tc * 4 + i]; }
#pragma unroll
            for (int i = 0; i < 4; i++)
#pragma unroll
                for (int j = 0; j < 4; j++) acc[i][j] += ra[i] * rb[j];
        }
        __syncthreads();
    }
#pragma unroll
    for (int i = 0; i < 4; i++) {
        int m = bm + tr * 4 + i;
#pragma unroll
        for (int j = 0; j < 4; j++) {
            int n = bn + tc * 4 + j;
            float v = acc[i][j];
            if (BIAS) v += bias[n];
            if (RELU) v = fmaxf(v, 0.f);
            if (RES)  v += R[m * N + n];
            C[m * N + n] = v;
        }
    }
}

// ---------------- encoder attention ----------------
__global__ void __launch_bounds__(128) enc_attn(const float* __restrict__ Q,
                                                const float* __restrict__ K,
                                                const float* __restrict__ V,
                                                float* __restrict__ O)
{
    __shared__ float Qs[SEQ][DHE], Ks[SEQ][DHE], Vs[SEQ][DHE];
    __shared__ float P[SEQ][SEQ + 1];
    int bh = blockIdx.x;
    int b = bh / NH, hh = bh % NH;
    int tid = threadIdx.x;
    for (int i = tid; i < SEQ * DHE; i += 128) {
        int s = i / DHE, j = i % DHE;
        int g = (b * SEQ + s) * DIM + hh * DHE + j;
        Qs[s][j] = Q[g]; Ks[s][j] = K[g]; Vs[s][j] = V[g];
    }
    __syncthreads();
    for (int p = tid; p < SEQ * SEQ; p += 128) {
        int q = p / SEQ, k = p % SEQ;
        float s = 0.f;
#pragma unroll
        for (int j = 0; j < DHE; j++) s += Qs[q][j] * Ks[k][j];
        P[q][k] = s * 0.25f;
    }
    __syncthreads();
    if (tid < SEQ) {
        float mx = -1e30f;
        for (int k = 0; k < SEQ; k++) mx = fmaxf(mx, P[tid][k]);
        float sum = 0.f;
        for (int k = 0; k < SEQ; k++) { float e = expf(P[tid][k] - mx); P[tid][k] = e; sum += e; }
        float inv = 1.f / sum;
        for (int k = 0; k < SEQ; k++) P[tid][k] *= inv;
    }
    __syncthreads();
    for (int p = tid; p < SEQ * DHE; p += 128) {
        int q = p / DHE, j = p % DHE;
        float s = 0.f;
        for (int k = 0; k < SEQ; k++) s += P[q][k] * Vs[k][j];
        O[(b * SEQ + q) * DIM + hh * DHE + j] = s;
    }
}

// ---------------- BatchNorm (deterministic 3-stage) ----------------
__global__ void __launch_bounds__(256) bn_partial(const float* __restrict__ X,
                                                  float* __restrict__ part)
{
    int d = threadIdx.x & 127, half = threadIdx.x >> 7;
    int r0 = blockIdx.x * 102;
    float s = 0.f, ss = 0.f;
    for (int r = r0 + half; r < r0 + 102; r += 2) {
        float v = X[r * DIM + d];
        s += v; ss += v * v;
    }
    __shared__ float sh[2][2][128];
    sh[half][0][d] = s; sh[half][1][d] = ss;
    __syncthreads();
    if (!half) {
        part[blockIdx.x * 256 + d]       = s + sh[1][0][d];
        part[blockIdx.x * 256 + 128 + d] = ss + sh[1][1][d];
    }
}

__global__ void bn_reduce(const float* __restrict__ part,
                          float* __restrict__ mean, float* __restrict__ rstd)
{
    int d = threadIdx.x;
    float s = 0.f, ss = 0.f;
    for (int b = 0; b < 64; b++) { s += part[b * 256 + d]; ss += part[b * 256 + 128 + d]; }
    float m = s * (1.f / (float)MTOT);
    float v = ss * (1.f / (float)MTOT) - m * m;
    mean[d] = m;
    rstd[d] = rsqrtf(v + 1e-5f);
}

__global__ void __launch_bounds__(256) bn_apply(const float* __restrict__ X,
                                                const float* __restrict__ mean,
                                                const float* __restrict__ rstd,
                                                const float* __restrict__ gamma,
                                                const float* __restrict__ beta,
                                                float* __restrict__ Y)
{
    int i = blockIdx.x * blockDim.x + threadIdx.x;
    if (i >= MTOT * DIM) return;
    int d = i & 127;
    Y[i] = gamma[d] * (X[i] - mean[d]) * rstd[d] + beta[d];
}

// ---------------- decoder: block-wide sum over 512 threads ----------------
__device__ __forceinline__ float blksum512(float v, float* red)
{
#pragma unroll
    for (int o = 16; o; o >>= 1) v += __shfl_down_sync(0xffffffffu, v, o);
    int w = threadIdx.x >> 5;
    if ((threadIdx.x & 31) == 0) red[w] = v;
    __syncthreads();
    float r = 0.f;
#pragma unroll
    for (int i = 0; i < 16; i++) r += red[i];
    __syncthreads();
    return r;
}

// 32-k-chunk partial of a [128 -> 128] GEMV, W row-major [k][128]
__device__ __forceinline__ float gemv_part(const float* __restrict__ x,
                                           const float* __restrict__ W,
                                           int d, int q)
{
    const float* Wp = W + (q * 32) * DIM + d;
    const float* xp = x + q * 32;
    float a = 0.f;
#pragma unroll
    for (int k = 0; k < 32; k++) a += xp[k] * Wp[k * DIM];
    return a;
}

// ---------------- persistent decoder: 1 batch element per block, 512 threads ----------------
__global__ void __launch_bounds__(512) decoder_kernel(
    const float* __restrict__ h_enc, const float* __restrict__ pe,
    const float* __restrict__ Katt, const float* __restrict__ Vatt,
    const float* __restrict__ Kfin,
    float* __restrict__ Kc, float* __restrict__ Vc,
    const float* __restrict__ dsw, const float* __restrict__ dsb,
    const float* __restrict__ dcw, const float* __restrict__ dcb,
    const float* __restrict__ dw1, const float* __restrict__ db1,
    const float* __restrict__ dw2, const float* __restrict__ db2,
    const float* __restrict__ dln, const float* __restrict__ wqf,
    float* __restrict__ out)
{
    int tid = threadIdx.x;
    int b = blockIdx.x;
    int d = tid & 127;           // output column
    int q = tid >> 7;            // k-chunk group 0..3
    int hh = d >> 4, dh = d & 15;

    __shared__ float ht[DIM], sq[DIM], so[DIM], su[DIM];
    __shared__ float sf[FFD];
    __shared__ float p0[4][DIM], p1[4][DIM], p2[4][DIM];
    __shared__ float sc[NH][SEQ + 1];
    __shared__ float red[16];
    __shared__ float slg[SEQ];
    __shared__ int   smask[SEQ];
    __shared__ int   scur;
    __shared__ float sslp;

    if (tid < SEQ) smask[tid] = (tid == NNOD) ? 1 : 0;
    if (tid == 0) { scur = NNOD; sslp = 0.f; }
    __syncthreads();

    for (int t = 0; t < NNOD; t++) {
        if (q == 0) ht[d] = h_enc[(b * SEQ + scur) * DIM + d] + pe[t * DIM + d];
        __syncthreads();

        for (int l = 0; l < NLD; l++) {
            const float* W  = dsw + l * 4 * DIM * DIM;
            const float* bb = dsb + l * 4 * DIM;

            // ---- QKV (three simultaneous split-K partials) ----
            p0[q][d] = gemv_part(ht, W,                 d, q);
            p1[q][d] = gemv_part(ht, W + DIM * DIM,     d, q);
            p2[q][d] = gemv_part(ht, W + 2 * DIM * DIM, d, q);
            __syncthreads();
            int cb = ((l * BB + b) * NH + hh) * NNOD * DHE;
            if (q == 0) {
                sq[d] = p0[0][d] + p0[1][d] + p0[2][d] + p0[3][d] + bb[d];
            } else if (q == 1) {
                Kc[cb + t * DHE + dh] = p1[0][d] + p1[1][d] + p1[2][d] + p1[3][d] + bb[DIM + d];
            } else if (q == 2) {
                Vc[cb + t * DHE + dh] = p2[0][d] + p2[1][d] + p2[2][d] + p2[3][d] + bb[2 * DIM + d];
            }
            __syncthreads();

            // ---- self-attn scores ----
            int nt = t + 1;
            if (tid < NH * nt) {
                int ph = tid / nt, ps = tid % nt;
                const float* kp = &Kc[((l * BB + b) * NH + ph) * NNOD * DHE + ps * DHE];
                const float* qp = &sq[ph * DHE];
                float s = 0.f;
#pragma unroll
                for (int j = 0; j < DHE; j++) s += qp[j] * kp[j];
                sc[ph][ps] = s * 0.25f;
            }
            __syncthreads();
            if (tid < NH) {
                float mx = -1e30f;
                for (int s = 0; s < nt; s++) mx = fmaxf(mx, sc[tid][s]);
                float sm = 0.f;
                for (int s = 0; s < nt; s++) { float e = expf(sc[tid][s] - mx); sc[tid][s] = e; sm += e; }
                float inv = 1.f / sm;
                for (int s = 0; s < nt; s++) sc[tid][s] *= inv;
            }
            __syncthreads();
            // ---- V-weighted sum, s-range split across q groups ----
            {
                int s0 = (nt * q) >> 2, s1 = (nt * (q + 1)) >> 2;
                const float* vp = &Vc[((l * BB + b) * NH + hh) * NNOD * DHE + dh];
                float oo = 0.f;
#pragma unroll 4
                for (int s = s0; s < s1; s++) oo += sc[hh][s] * vp[s * DHE];
                p0[q][d] = oo;
            }
            __syncthreads();
            if (q == 0) so[d] = p0[0][d] + p0[1][d] + p0[2][d] + p0[3][d];
            __syncthreads();
            // ---- Wo + residual ----
            p0[q][d] = gemv_part(so, W + 3 * DIM * DIM, d, q);
            __syncthreads();
            if (q == 0) su[d] = ht[d] + p0[0][d] + p0[1][d] + p0[2][d] + p0[3][d] + bb[3 * DIM + d];
            __syncthreads();
            {
                const float* gb = dln + ((l * 3 + 0) * 2) * DIM;
                float mean = blksum512(su[d], red) * (1.f / 512.f);
                float diff = su[d] - mean;
                float var = blksum512(diff * diff, red) * (1.f / 512.f);
                float rstd = rsqrtf(var + 1e-5f);
                if (q == 0) ht[d] = gb[d] * diff * rstd + gb[DIM + d];
                __syncthreads();
            }

            // ---- cross attention ----
            const float* Wc = dcw + l * 2 * DIM * DIM;
            const float* bc = dcb + l * 2 * DIM;
            p0[q][d] = gemv_part(ht, Wc, d, q);
            __syncthreads();
            if (q == 0) sq[d] = p0[0][d] + p0[1][d] + p0[2][d] + p0[3][d] + bc[d];
            __syncthreads();
            if (tid < NH * SEQ) {
                int ph = tid / SEQ, pn = tid % SEQ;
                const float* kp = &Katt[(b * SEQ + pn) * (NLD * DIM) + l * DIM + ph * DHE];
                const float* qp = &sq[ph * DHE];
                float s = 0.f;
#pragma unroll
                for (int j = 0; j < DHE; j++) s += qp[j] * kp[j];
                sc[ph][pn] = s * 0.25f;
            }
            __syncthreads();
            if (tid < NH) {
                float mx = -1e30f;
                for (int n = 0; n < SEQ; n++) mx = fmaxf(mx, sc[tid][n]);
                float sm = 0.f;
                for (int n = 0; n < SEQ; n++) { float e = expf(sc[tid][n] - mx); sc[tid][n] = e; sm += e; }
                float inv = 1.f / sm;
                for (int n = 0; n < SEQ; n++) sc[tid][n] *= inv;
            }
            __syncthreads();
            {
                int s0 = (SEQ * q) >> 2, s1 = (SEQ * (q + 1)) >> 2;
                const float* vp = &Vatt[b * SEQ * (NLD * DIM) + l * DIM + d];
                float oo = 0.f;
#pragma unroll 4
                for (int n = s0; n < s1; n++) oo += sc[hh][n] * vp[n * NLD * DIM];
                p0[q][d] = oo;
            }
            __syncthreads();
            if (q == 0) so[d] = p0[0][d] + p0[1][d] + p0[2][d] + p0[3][d];
            __syncthreads();
            p0[q][d] = gemv_part(so, Wc + DIM * DIM, d, q);
            __syncthreads();
            if (q == 0) su[d] = ht[d] + p0[0][d] + p0[1][d] + p0[2][d] + p0[3][d] + bc[DIM + d];
            __syncthreads();
            {
                const float* gb = dln + ((l * 3 + 1) * 2) * DIM;
                float mean = blksum512(su[d], red) * (1.f / 512.f);
                float diff = su[d] - mean;
                float var = blksum512(diff * diff, red) * (1.f / 512.f);
                float rstd = rsqrtf(var + 1e-5f);
                if (q == 0) ht[d] = gb[d] * diff * rstd + gb[DIM + d];
                __syncthreads();
            }

            // ---- FFN1: each of 512 threads computes one hidden unit ----
            {
                const float* W1p = dw1 + l * DIM * FFD + tid;
                float a = db1[l * FFD + tid];
#pragma unroll 16
                for (int k = 0; k < DIM; k++) a += ht[k] * W1p[k * FFD];
                sf[tid] = fmaxf(a, 0.f);
            }
            __syncthreads();
            // ---- FFN2: 4-way split-K over 512 ----
            {
                const float* W2p = dw2 + l * FFD * DIM + (q * 128) * DIM + d;
                const float* xp = sf + q * 128;
                float a = 0.f;
#pragma unroll 16
                for (int k = 0; k < 128; k++) a += xp[k] * W2p[k * DIM];
                p0[q][d] = a;
            }
            __syncthreads();
            if (q == 0) su[d] = ht[d] + p0[0][d] + p0[1][d] + p0[2][d] + p0[3][d] + db2[l * DIM + d];
            __syncthreads();
            {
                const float* gb = dln + ((l * 3 + 2) * 2) * DIM;
                float mean = blksum512(su[d], red) * (1.f / 512.f);
                float diff = su[d] - mean;
                float var = blksum512(diff * diff, red) * (1.f / 512.f);
                float rstd = rsqrtf(var + 1e-5f);
                if (q == 0) ht[d] = gb[d] * diff * rstd + gb[DIM + d];
                __syncthreads();
            }
        }

        // ---- final pointer logits ----
        p0[q][d] = gemv_part(ht, wqf, d, q);
        __syncthreads();
        if (q == 0) sq[d] = p0[0][d] + p0[1][d] + p0[2][d] + p0[3][d];
        __syncthreads();
        if (tid < SEQ) {
            const float4* kp = (const float4*)&Kfin[(b * SEQ + tid) * DIM];
            float s = 0.f;
#pragma unroll
            for (int k = 0; k < 32; k++) {
                float4 kv = kp[k];
                s += sq[4 * k] * kv.x + sq[4 * k + 1] * kv.y
                   + sq[4 * k + 2] * kv.z + sq[4 * k + 3] * kv.w;
            }
            float lg = 10.f * tanhf(s * 0.08838834764831845f);   // 1/sqrt(128)
            slg[tid] = smask[tid] ? -1e9f : lg;
        }
        __syncthreads();
        if (tid == 0) {
            float mx = -1e30f;
            int am = 0;
            for (int n = 0; n < SEQ; n++) if (slg[n] > mx) { mx = slg[n]; am = n; }
            float sm = 0.f;
            for (int n = 0; n < SEQ; n++) sm += expf(slg[n] - mx);
            sslp += -logf(sm);      // logp[argmax] = -log(sum exp(l - max))
            smask[am] = 1;
            scur = am;
            out[b * NNOD + t] = (float)am;
        }
        __syncthreads();
    }
    if (tid == 0) out[BB * NNOD + b] = sslp;
}

// ---------------- host launcher ----------------
extern "C" void kernel_launch(void* const* d_in, const int* in_sizes, int n_in,
                              void* d_out, int out_size)
{
    const float* x          = (const float*)d_in[0];
    const float* w_input    = (const float*)d_in[1];
    const float* b_input    = (const float*)d_in[2];
    const float* start_ph   = (const float*)d_in[3];
    const float* enc_attn_w = (const float*)d_in[4];
    const float* enc_attn_b = (const float*)d_in[5];
    const float* enc_ffn_w1 = (const float*)d_in[6];
    const float* enc_ffn_b1 = (const float*)d_in[7];
    const float* enc_ffn_w2 = (const float*)d_in[8];
    const float* enc_ffn_b2 = (const float*)d_in[9];
    const float* enc_bn     = (const float*)d_in[10];
    const float* dec_self_w = (const float*)d_in[11];
    const float* dec_self_b = (const float*)d_in[12];
    const float* dec_cross_w= (const float*)d_in[13];
    const float* dec_cross_b= (const float*)d_in[14];
    const float* dec_ffn_w1 = (const float*)d_in[15];
    const float* dec_ffn_b1 = (const float*)d_in[16];
    const float* dec_ffn_w2 = (const float*)d_in[17];
    const float* dec_ffn_b2 = (const float*)d_in[18];
    const float* dec_ln     = (const float*)d_in[19];
    const float* wk_dec     = (const float*)d_in[20];
    const float* bk_dec     = (const float*)d_in[21];
    const float* wv_dec     = (const float*)d_in[22];
    const float* bv_dec     = (const float*)d_in[23];
    const float* wq_final   = (const float*)d_in[24];
    const float* wk_final   = (const float*)d_in[25];
    float* out = (float*)d_out;

    float* base = nullptr;
    cudaGetSymbolAddress((void**)&base, g_scratch);
    float* ph    = base;
    float* pt    = base + OFF_T;
    float* pQ    = base + OFF_Q;
    float* pf    = base + OFF_F;
    float* pKatt = base + OFF_KATT;
    float* pVatt = base + OFF_VATT;
    float* pKfin = base + OFF_KFIN;
    float* ppart = base + OFF_PART;
    float* pmean = base + OFF_MEAN;
    float* prstd = base + OFF_RSTD;
    float* ppe   = base + OFF_PE;
    float* pKc   = base + OFF_KC;
    float* pVc   = base + OFF_VC;

    embed_kernel<<<(MTOT * DIM + 255) / 256, 256>>>(x, w_input, b_input, start_ph, ph);
    pe_kernel<<<(NNOD * DIM + 255) / 256, 256>>>(ppe);

    dim3 gDD(DIM / 64, MTOT / 64);            // N=128
    dim3 gQKV(DIM / 64, MTOT / 64, 3);        // fused Q,K,V
    dim3 gDF(FFD / 64, MTOT / 64);            // N=512
    dim3 gD2(256 / 64, MTOT / 64);            // N=256

    for (int l = 0; l < NLE; l++) {
        const float* aw = enc_attn_w + (size_t)l * 4 * DIM * DIM;
        const float* ab = enc_attn_b + (size_t)l * 4 * DIM;
        sgemm<true, false, false, true><<<gQKV, 256>>>(ph, aw, ab, nullptr, pQ, MTOT, DIM, DIM);
        enc_attn<<<BB * NH, 128>>>(pQ, pQ + SZ_MD, pQ + 2 * SZ_MD, base + OFF_O);
        sgemm<true, false, true, false><<<gDD, 256>>>(base + OFF_O, aw + 3 * DIM * DIM,
                 ab + 3 * DIM, ph, pt, MTOT, DIM, DIM);
        bn_partial<<<64, 256>>>(pt, ppart);
        bn_reduce<<<1, 128>>>(ppart, pmean, prstd);
        bn_apply<<<(MTOT * DIM + 255) / 256, 256>>>(pt, pmean, prstd,
                 enc_bn + ((l * 2 + 0) * 2 + 0) * DIM, enc_bn + ((l * 2 + 0) * 2 + 1) * DIM, ph);
        sgemm<true, true, false, false><<<gDF, 256>>>(ph, enc_ffn_w1 + (size_t)l * DIM * FFD,
                 enc_ffn_b1 + (size_t)l * FFD, nullptr, pf, MTOT, FFD, DIM);
        sgemm<true, false, true, false><<<gDD, 256>>>(pf, enc_ffn_w2 + (size_t)l * FFD * DIM,
                 enc_ffn_b2 + (size_t)l * DIM, ph, pt, MTOT, DIM, FFD);
        bn_partial<<<64, 256>>>(pt, ppart);
        bn_reduce<<<1, 128>>>(ppart, pmean, prstd);
        bn_apply<<<(MTOT * DIM + 255) / 256, 256>>>(pt, pmean, prstd,
                 enc_bn + ((l * 2 + 1) * 2 + 0) * DIM, enc_bn + ((l * 2 + 1) * 2 + 1) * DIM, ph);
    }

    sgemm<true,  false, false, false><<<gD2, 256>>>(ph, wk_dec,   bk_dec,  nullptr, pKatt, MTOT, NLD * DIM, DIM);
    sgemm<true,  false, false, false><<<gD2, 256>>>(ph, wv_dec,   bv_dec,  nullptr, pVatt, MTOT, NLD * DIM, DIM);
    sgemm<false, false, false, false><<<gDD, 256>>>(ph, wk_final, nullptr, nullptr, pKfin, MTOT, DIM, DIM);

    decoder_kernel<<<BB, 512>>>(ph, ppe, pKatt, pVatt, pKfin, pKc, pVc,
                                dec_self_w, dec_self_b, dec_cross_w, dec_cross_b,
                                dec_ffn_w1, dec_ffn_b1, dec_ffn_w2, dec_ffn_b2,
                                dec_ln, wq_final, out);
}

// round 6
// speedup vs baseline: 2.8408x; 1.0675x over previous
#include <cuda_runtime.h>
#include <math.h>

#define BB   128
#define NNOD 50
#define SEQ  51
#define DIM  128
#define NH   8
#define DHE  16
#define FFD  512
#define NLE  6
#define NLD  2
#define MTOT (BB*SEQ)            // 6528
#define SZ_MD (MTOT*DIM)         // 835584

// ---------------- scratch ----------------
#define OFF_T    (SZ_MD)
#define OFF_Q    (2*SZ_MD)
#define OFF_O    (5*SZ_MD)
#define OFF_F    (6*SZ_MD)
#define OFF_KATT (10*SZ_MD)
#define OFF_VATT (12*SZ_MD)
#define OFF_KFIN (14*SZ_MD)
#define OFF_PART (15*SZ_MD)
#define OFF_MEAN (OFF_PART + 16384)
#define OFF_RSTD (OFF_MEAN + 128)
#define OFF_PE   (OFF_RSTD + 128)
#define OFF_KC   (OFF_PE + NNOD*DIM)
#define SZ_KC    (NLD*BB*NH*NNOD*DHE)
#define OFF_VC   (OFF_KC + SZ_KC)
#define SCRATCH_TOTAL (OFF_VC + SZ_KC)

__device__ float g_scratch[SCRATCH_TOTAL];

// ---------------- embedding ----------------
__global__ void embed_kernel(const float* __restrict__ x,
                             const float* __restrict__ w_in,
                             const float* __restrict__ b_in,
                             const float* __restrict__ start_ph,
                             float* __restrict__ h)
{
    int i = blockIdx.x * blockDim.x + threadIdx.x;
    if (i >= MTOT * DIM) return;
    int d = i & 127;
    int row = i >> 7;
    int s = row % SEQ;
    int b = row / SEQ;
    float v;
    if (s < NNOD) {
        const float* xp = x + (b * NNOD + s) * 2;
        v = xp[0] * w_in[d] + xp[1] * w_in[DIM + d] + b_in[d];
    } else {
        v = start_ph[d];
    }
    h[i] = v;
}

// ---------------- positional encoding ----------------
__global__ void pe_kernel(float* __restrict__ pe)
{
    int i = blockIdx.x * blockDim.x + threadIdx.x;
    if (i >= NNOD * DIM) return;
    int t = i >> 7, d = i & 127;
    double e = (double)(2 * (d / 2)) / 128.0;
    double ang = (double)t * pow(10000.0, -e);
    pe[i] = (float)(((d & 1) == 0) ? sin(ang) : cos(ang));
}

// ---------------- SGEMM: C = A[M,K] @ W[K,N] (+bias)(relu)(+res) ----------------
template<bool BIAS, bool RELU, bool RES, bool ZSTRIDE>
__global__ void __launch_bounds__(256) sgemm(const float* __restrict__ A,
                                             const float* __restrict__ W,
                                             const float* __restrict__ bias,
                                             const float* __restrict__ R,
                                             float* __restrict__ C,
                                             int M, int N, int K)
{
    if (ZSTRIDE) {
        int z = blockIdx.z;
        W += (size_t)z * K * N;
        if (BIAS) bias += (size_t)z * N;
        C += (size_t)z * M * N;
    }
    __shared__ float As[16][68];
    __shared__ float Bs[16][68];
    int bm = blockIdx.y * 64, bn = blockIdx.x * 64;
    int tid = threadIdx.x;
    int tr = tid >> 4, tc = tid & 15;
    float acc[4][4] = {};
    for (int k0 = 0; k0 < K; k0 += 16) {
        int m = tid >> 2, kk = (tid & 3) * 4;
        float4 av = *(const float4*)&A[(bm + m) * K + k0 + kk];
        As[kk + 0][m] = av.x; As[kk + 1][m] = av.y;
        As[kk + 2][m] = av.z; As[kk + 3][m] = av.w;
        int kr = tid >> 4, cc = (tid & 15) * 4;
        float4 bv = *(const float4*)&W[(k0 + kr) * N + bn + cc];
        Bs[kr][cc + 0] = bv.x; Bs[kr][cc + 1] = bv.y;
        Bs[kr][cc + 2] = bv.z; Bs[kr][cc + 3] = bv.w;
        __syncthreads();
#pragma unroll
        for (int k2 = 0; k2 < 16; k2++) {
            float ra[4], rb[4];
#pragma unroll
            for (int i = 0; i < 4; i++) { ra[i] = As[k2][tr * 4 + i]; rb[i] = Bs[k2][tc * 4 + i]; }
#pragma unroll
            for (int i = 0; i < 4; i++)
#pragma unroll
                for (int j = 0; j < 4; j++) acc[i][j] += ra[i] * rb[j];
        }
        __syncthreads();
    }
#pragma unroll
    for (int i = 0; i < 4; i++) {
        int m = bm + tr * 4 + i;
#pragma unroll
        for (int j = 0; j < 4; j++) {
            int n = bn + tc * 4 + j;
            float v = acc[i][j];
            if (BIAS) v += bias[n];
            if (RELU) v = fmaxf(v, 0.f);
            if (RES)  v += R[m * N + n];
            C[m * N + n] = v;
        }
    }
}

// ---------------- encoder attention ----------------
__global__ void __launch_bounds__(128) enc_attn(const float* __restrict__ Q,
                                                const float* __restrict__ K,
                                                const float* __restrict__ V,
                                                float* __restrict__ O)
{
    __shared__ float Qs[SEQ][DHE], Ks[SEQ][DHE], Vs[SEQ][DHE];
    __shared__ float P[SEQ][SEQ + 1];
    int bh = blockIdx.x;
    int b = bh / NH, hh = bh % NH;
    int tid = threadIdx.x;
    for (int i = tid; i < SEQ * DHE; i += 128) {
        int s = i / DHE, j = i % DHE;
        int g = (b * SEQ + s) * DIM + hh * DHE + j;
        Qs[s][j] = Q[g]; Ks[s][j] = K[g]; Vs[s][j] = V[g];
    }
    __syncthreads();
    for (int p = tid; p < SEQ * SEQ; p += 128) {
        int q = p / SEQ, k = p % SEQ;
        float s = 0.f;
#pragma unroll
        for (int j = 0; j < DHE; j++) s += Qs[q][j] * Ks[k][j];
        P[q][k] = s * 0.25f;
    }
    __syncthreads();
    if (tid < SEQ) {
        float mx = -1e30f;
        for (int k = 0; k < SEQ; k++) mx = fmaxf(mx, P[tid][k]);
        float sum = 0.f;
        for (int k = 0; k < SEQ; k++) { float e = expf(P[tid][k] - mx); P[tid][k] = e; sum += e; }
        float inv = 1.f / sum;
        for (int k = 0; k < SEQ; k++) P[tid][k] *= inv;
    }
    __syncthreads();
    for (int p = tid; p < SEQ * DHE; p += 128) {
        int q = p / DHE, j = p % DHE;
        float s = 0.f;
        for (int k = 0; k < SEQ; k++) s += P[q][k] * Vs[k][j];
        O[(b * SEQ + q) * DIM + hh * DHE + j] = s;
    }
}

// ---------------- BatchNorm (deterministic 3-stage) ----------------
__global__ void __launch_bounds__(256) bn_partial(const float* __restrict__ X,
                                                  float* __restrict__ part)
{
    int d = threadIdx.x & 127, half = threadIdx.x >> 7;
    int r0 = blockIdx.x * 102;
    float s = 0.f, ss = 0.f;
    for (int r = r0 + half; r < r0 + 102; r += 2) {
        float v = X[r * DIM + d];
        s += v; ss += v * v;
    }
    __shared__ float sh[2][2][128];
    sh[half][0][d] = s; sh[half][1][d] = ss;
    __syncthreads();
    if (!half) {
        part[blockIdx.x * 256 + d]       = s + sh[1][0][d];
        part[blockIdx.x * 256 + 128 + d] = ss + sh[1][1][d];
    }
}

__global__ void bn_reduce(const float* __restrict__ part,
                          float* __restrict__ mean, float* __restrict__ rstd)
{
    int d = threadIdx.x;
    float s = 0.f, ss = 0.f;
    for (int b = 0; b < 64; b++) { s += part[b * 256 + d]; ss += part[b * 256 + 128 + d]; }
    float m = s * (1.f / (float)MTOT);
    float v = ss * (1.f / (float)MTOT) - m * m;
    mean[d] = m;
    rstd[d] = rsqrtf(v + 1e-5f);
}

__global__ void __launch_bounds__(256) bn_apply(const float* __restrict__ X,
                                                const float* __restrict__ mean,
                                                const float* __restrict__ rstd,
                                                const float* __restrict__ gamma,
                                                const float* __restrict__ beta,
                                                float* __restrict__ Y)
{
    int i = blockIdx.x * blockDim.x + threadIdx.x;
    if (i >= MTOT * DIM) return;
    int d = i & 127;
    Y[i] = gamma[d] * (X[i] - mean[d]) * rstd[d] + beta[d];
}

// ---------------- decoder helpers ----------------
__device__ __forceinline__ float blksum512(float v, float* red)
{
#pragma unroll
    for (int o = 16; o; o >>= 1) v += __shfl_down_sync(0xffffffffu, v, o);
    int w = threadIdx.x >> 5;
    if ((threadIdx.x & 31) == 0) red[w] = v;
    __syncthreads();
    float r = 0.f;
#pragma unroll
    for (int i = 0; i < 16; i++) r += red[i];
    __syncthreads();
    return r;
}

// float4 partial of a [128 -> 128] GEMV: 32 col-groups (c) x 16 k-groups (q16), 8 k each.
// acc[0..3] += sum_k x[k] * W[k][4c .. 4c+3]
__device__ __forceinline__ void gemv4_part(const float* __restrict__ x,
                                           const float* __restrict__ W,
                                           int c, int q16, float* acc)
{
    const float4* Wp = (const float4*)(W + (q16 * 8) * DIM) + c;
    const float* xp = x + q16 * 8;
#pragma unroll
    for (int k = 0; k < 8; k++) {
        float xk = xp[k];
        float4 w = Wp[k * 32];
        acc[0] += xk * w.x; acc[1] += xk * w.y;
        acc[2] += xk * w.z; acc[3] += xk * w.w;
    }
}

// ---------------- persistent decoder: 1 batch element per block, 512 threads ----------------
__global__ void __launch_bounds__(512) decoder_kernel(
    const float* __restrict__ h_enc, const float* __restrict__ pe,
    const float* __restrict__ Katt, const float* __restrict__ Vatt,
    const float* __restrict__ Kfin,
    float* __restrict__ Kc, float* __restrict__ Vc,
    const float* __restrict__ dsw, const float* __restrict__ dsb,
    const float* __restrict__ dcw, const float* __restrict__ dcb,
    const float* __restrict__ dw1, const float* __restrict__ db1,
    const float* __restrict__ dw2, const float* __restrict__ db2,
    const float* __restrict__ dln, const float* __restrict__ wqf,
    float* __restrict__ out)
{
    int tid = threadIdx.x;
    int b = blockIdx.x;
    int d = tid & 127;           // output column (combine phases)
    int q4 = tid >> 7;           // 4-way group (attention splits / FFN1 k-groups)
    int c = tid & 31;            // col-group: columns 4c..4c+3
    int q16 = tid >> 5;          // 16-way k-group
    int hh = d >> 4, dh = d & 15;

    __shared__ float ht[DIM], sq[DIM], so[DIM], su[DIM];
    __shared__ float sf[FFD];
    __shared__ float pb0[2048], pb1[2048], pb2[2048];   // partial buffers
    __shared__ float sc[NH][SEQ + 1];
    __shared__ float red[16];
    __shared__ float slg[SEQ];
    __shared__ int   smask[SEQ];
    __shared__ int   scur;
    __shared__ float sslp;

    if (tid < SEQ) smask[tid] = (tid == NNOD) ? 1 : 0;
    if (tid == 0) { scur = NNOD; sslp = 0.f; }
    __syncthreads();

    for (int t = 0; t < NNOD; t++) {
        if (q4 == 0) ht[d] = h_enc[(b * SEQ + scur) * DIM + d] + pe[t * DIM + d];
        __syncthreads();

        for (int l = 0; l < NLD; l++) {
            const float* W  = dsw + l * 4 * DIM * DIM;
            const float* bb = dsb + l * 4 * DIM;

            // ---- QKV: three simultaneous float4 split-K partials ----
            {
                float aq[4] = {}, ak[4] = {}, av[4] = {};
                gemv4_part(ht, W,                 c, q16, aq);
                gemv4_part(ht, W + DIM * DIM,     c, q16, ak);
                gemv4_part(ht, W + 2 * DIM * DIM, c, q16, av);
                *(float4*)&pb0[q16 * 128 + c * 4] = make_float4(aq[0], aq[1], aq[2], aq[3]);
                *(float4*)&pb1[q16 * 128 + c * 4] = make_float4(ak[0], ak[1], ak[2], ak[3]);
                *(float4*)&pb2[q16 * 128 + c * 4] = make_float4(av[0], av[1], av[2], av[3]);
            }
            __syncthreads();
            {
                int cb = ((l * BB + b) * NH) * NNOD * DHE;
                if (tid < 128) {
                    float s = bb[tid];
#pragma unroll
                    for (int qq = 0; qq < 16; qq++) s += pb0[qq * 128 + tid];
                    sq[tid] = s;
                } else if (tid < 256) {
                    int dd = tid - 128;
                    float s = bb[DIM + dd];
#pragma unroll
                    for (int qq = 0; qq < 16; qq++) s += pb1[qq * 128 + dd];
                    Kc[cb + (dd >> 4) * NNOD * DHE + t * DHE + (dd & 15)] = s;
                } else if (tid < 384) {
                    int dd = tid - 256;
                    float s = bb[2 * DIM + dd];
#pragma unroll
                    for (int qq = 0; qq < 16; qq++) s += pb2[qq * 128 + dd];
                    Vc[cb + (dd >> 4) * NNOD * DHE + t * DHE + (dd & 15)] = s;
                }
            }
            __syncthreads();

            // ---- self-attn scores ----
            int nt = t + 1;
            if (tid < NH * nt) {
                int ph = tid / nt, ps = tid % nt;
                const float* kp = &Kc[((l * BB + b) * NH + ph) * NNOD * DHE + ps * DHE];
                const float* qp = &sq[ph * DHE];
                float s = 0.f;
#pragma unroll
                for (int j = 0; j < DHE; j++) s += qp[j] * kp[j];
                sc[ph][ps] = s * 0.25f;
            }
            __syncthreads();
            if (tid < NH) {
                float mx = -1e30f;
                for (int s = 0; s < nt; s++) mx = fmaxf(mx, sc[tid][s]);
                float sm = 0.f;
                for (int s = 0; s < nt; s++) { float e = expf(sc[tid][s] - mx); sc[tid][s] = e; sm += e; }
                float inv = 1.f / sm;
                for (int s = 0; s < nt; s++) sc[tid][s] *= inv;
            }
            __syncthreads();
            // ---- V-weighted sum, s-range split across q4 groups ----
            {
                int s0 = (nt * q4) >> 2, s1 = (nt * (q4 + 1)) >> 2;
                const float* vp = &Vc[((l * BB + b) * NH + hh) * NNOD * DHE + dh];
                float oo = 0.f;
#pragma unroll 4
                for (int s = s0; s < s1; s++) oo += sc[hh][s] * vp[s * DHE];
                pb0[q4 * 128 + d] = oo;
            }
            __syncthreads();
            if (tid < 128) so[tid] = pb0[tid] + pb0[128 + tid] + pb0[256 + tid] + pb0[384 + tid];
            __syncthreads();
            // ---- Wo + residual ----
            {
                float a[4] = {};
                gemv4_part(so, W + 3 * DIM * DIM, c, q16, a);
                *(float4*)&pb0[q16 * 128 + c * 4] = make_float4(a[0], a[1], a[2], a[3]);
            }
            __syncthreads();
            if (tid < 128) {
                float s = ht[tid] + bb[3 * DIM + tid];
#pragma unroll
                for (int qq = 0; qq < 16; qq++) s += pb0[qq * 128 + tid];
                su[tid] = s;
            }
            __syncthreads();
            {
                const float* gb = dln + ((l * 3 + 0) * 2) * DIM;
                float mean = blksum512(su[d], red) * (1.f / 512.f);
                float diff = su[d] - mean;
                float var = blksum512(diff * diff, red) * (1.f / 512.f);
                float rstd = rsqrtf(var + 1e-5f);
                if (q4 == 0) ht[d] = gb[d] * diff * rstd + gb[DIM + d];
                __syncthreads();
            }

            // ---- cross attention ----
            const float* Wc = dcw + l * 2 * DIM * DIM;
            const float* bc = dcb + l * 2 * DIM;
            {
                float a[4] = {};
                gemv4_part(ht, Wc, c, q16, a);
                *(float4*)&pb0[q16 * 128 + c * 4] = make_float4(a[0], a[1], a[2], a[3]);
            }
            __syncthreads();
            if (tid < 128) {
                float s = bc[tid];
#pragma unroll
                for (int qq = 0; qq < 16; qq++) s += pb0[qq * 128 + tid];
                sq[tid] = s;
            }
            __syncthreads();
            if (tid < NH * SEQ) {
                int ph = tid / SEQ, pn = tid % SEQ;
                const float* kp = &Katt[(b * SEQ + pn) * (NLD * DIM) + l * DIM + ph * DHE];
                const float* qp = &sq[ph * DHE];
                float s = 0.f;
#pragma unroll
                for (int j = 0; j < DHE; j++) s += qp[j] * kp[j];
                sc[ph][pn] = s * 0.25f;
            }
            __syncthreads();
            if (tid < NH) {
                float mx = -1e30f;
                for (int n = 0; n < SEQ; n++) mx = fmaxf(mx, sc[tid][n]);
                float sm = 0.f;
                for (int n = 0; n < SEQ; n++) { float e = expf(sc[tid][n] - mx); sc[tid][n] = e; sm += e; }
                float inv = 1.f / sm;
                for (int n = 0; n < SEQ; n++) sc[tid][n] *= inv;
            }
            __syncthreads();
            {
                int s0 = (SEQ * q4) >> 2, s1 = (SEQ * (q4 + 1)) >> 2;
                const float* vp = &Vatt[b * SEQ * (NLD * DIM) + l * DIM + d];
                float oo = 0.f;
#pragma unroll 4
                for (int n = s0; n < s1; n++) oo += sc[hh][n] * vp[n * NLD * DIM];
                pb0[q4 * 128 + d] = oo;
            }
            __syncthreads();
            if (tid < 128) so[tid] = pb0[tid] + pb0[128 + tid] + pb0[256 + tid] + pb0[384 + tid];
            __syncthreads();
            {
                float a[4] = {};
                gemv4_part(so, Wc + DIM * DIM, c, q16, a);
                *(float4*)&pb0[q16 * 128 + c * 4] = make_float4(a[0], a[1], a[2], a[3]);
            }
            __syncthreads();
            if (tid < 128) {
                float s = ht[tid] + bc[DIM + tid];
#pragma unroll
                for (int qq = 0; qq < 16; qq++) s += pb0[qq * 128 + tid];
                su[tid] = s;
            }
            __syncthreads();
            {
                const float* gb = dln + ((l * 3 + 1) * 2) * DIM;
                float mean = blksum512(su[d], red) * (1.f / 512.f);
                float diff = su[d] - mean;
                float var = blksum512(diff * diff, red) * (1.f / 512.f);
                float rstd = rsqrtf(var + 1e-5f);
                if (q4 == 0) ht[d] = gb[d] * diff * rstd + gb[DIM + d];
                __syncthreads();
            }

            // ---- FFN1: [128 -> 512], 128 col-groups (cc) x 4 k-groups (q4), 32 k each ----
            {
                int cc = tid & 127;
                const float* W1 = dw1 + l * DIM * FFD;
                const float4* Wp = (const float4*)(W1 + (q4 * 32) * FFD) + cc;
                const float* xp = ht + q4 * 32;
                float a[4] = {};
#pragma unroll
                for (int k = 0; k < 32; k++) {
                    float xk = xp[k];
                    float4 w = Wp[k * 128];
                    a[0] += xk * w.x; a[1] += xk * w.y;
                    a[2] += xk * w.z; a[3] += xk * w.w;
                }
                *(float4*)&pb0[q4 * 512 + cc * 4] = make_float4(a[0], a[1], a[2], a[3]);
            }
            __syncthreads();
            sf[tid] = fmaxf(db1[l * FFD + tid] + pb0[tid] + pb0[512 + tid]
                            + pb0[1024 + tid] + pb0[1536 + tid], 0.f);
            __syncthreads();
            // ---- FFN2: [512 -> 128], 32 col-groups (c) x 16 k-groups (q16), 32 k each ----
            {
                const float* W2 = dw2 + l * FFD * DIM;
                const float4* Wp = (const float4*)(W2 + (q16 * 32) * DIM) + c;
                const float* xp = sf + q16 * 32;
                float a[4] = {};
#pragma unroll
                for (int k = 0; k < 32; k++) {
                    float xk = xp[k];
                    float4 w = Wp[k * 32];
                    a[0] += xk * w.x; a[1] += xk * w.y;
                    a[2] += xk * w.z; a[3] += xk * w.w;
                }
                *(float4*)&pb0[q16 * 128 + c * 4] = make_float4(a[0], a[1], a[2], a[3]);
            }
            __syncthreads();
            if (tid < 128) {
                float s = ht[tid] + db2[l * DIM + tid];
#pragma unroll
                for (int qq = 0; qq < 16; qq++) s += pb0[qq * 128 + tid];
                su[tid] = s;
            }
            __syncthreads();
            {
                const float* gb = dln + ((l * 3 + 2) * 2) * DIM;
                float mean = blksum512(su[d], red) * (1.f / 512.f);
                float diff = su[d] - mean;
                float var = blksum512(diff * diff, red) * (1.f / 512.f);
                float rstd = rsqrtf(var + 1e-5f);
                if (q4 == 0) ht[d] = gb[d] * diff * rstd + gb[DIM + d];
                __syncthreads();
            }
        }

        // ---- final pointer logits ----
        {
            float a[4] = {};
            gemv4_part(ht, wqf, c, q16, a);
            *(float4*)&pb0[q16 * 128 + c * 4] = make_float4(a[0], a[1], a[2], a[3]);
        }
        __syncthreads();
        if (tid < 128) {
            float s = 0.f;
#pragma unroll
            for (int qq = 0; qq < 16; qq++) s += pb0[qq * 128 + tid];
            sq[tid] = s;
        }
        __syncthreads();
        if (tid < SEQ) {
            const float4* kp = (const float4*)&Kfin[(b * SEQ + tid) * DIM];
            float s = 0.f;
#pragma unroll
            for (int k = 0; k < 32; k++) {
                float4 kv = kp[k];
                s += sq[4 * k] * kv.x + sq[4 * k + 1] * kv.y
                   + sq[4 * k + 2] * kv.z + sq[4 * k + 3] * kv.w;
            }
            float lg = 10.f * tanhf(s * 0.08838834764831845f);   // 1/sqrt(128)
            slg[tid] = smask[tid] ? -1e9f : lg;
        }
        __syncthreads();
        if (tid == 0) {
            float mx = -1e30f;
            int am = 0;
            for (int n = 0; n < SEQ; n++) if (slg[n] > mx) { mx = slg[n]; am = n; }
            float sm = 0.f;
            for (int n = 0; n < SEQ; n++) sm += expf(slg[n] - mx);
            sslp += -logf(sm);      // logp[argmax] = -log(sum exp(l - max))
            smask[am] = 1;
            scur = am;
            out[b * NNOD + t] = (float)am;
        }
        __syncthreads();
    }
    if (tid == 0) out[BB * NNOD + b] = sslp;
}

// ---------------- host launcher ----------------
extern "C" void kernel_launch(void* const* d_in, const int* in_sizes, int n_in,
                              void* d_out, int out_size)
{
    const float* x          = (const float*)d_in[0];
    const float* w_input    = (const float*)d_in[1];
    const float* b_input    = (const float*)d_in[2];
    const float* start_ph   = (const float*)d_in[3];
    const float* enc_attn_w = (const float*)d_in[4];
    const float* enc_attn_b = (const float*)d_in[5];
    const float* enc_ffn_w1 = (const float*)d_in[6];
    const float* enc_ffn_b1 = (const float*)d_in[7];
    const float* enc_ffn_w2 = (const float*)d_in[8];
    const float* enc_ffn_b2 = (const float*)d_in[9];
    const float* enc_bn     = (const float*)d_in[10];
    const float* dec_self_w = (const float*)d_in[11];
    const float* dec_self_b = (const float*)d_in[12];
    const float* dec_cross_w= (const float*)d_in[13];
    const float* dec_cross_b= (const float*)d_in[14];
    const float* dec_ffn_w1 = (const float*)d_in[15];
    const float* dec_ffn_b1 = (const float*)d_in[16];
    const float* dec_ffn_w2 = (const float*)d_in[17];
    const float* dec_ffn_b2 = (const float*)d_in[18];
    const float* dec_ln     = (const float*)d_in[19];
    const float* wk_dec     = (const float*)d_in[20];
    const float* bk_dec     = (const float*)d_in[21];
    const float* wv_dec     = (const float*)d_in[22];
    const float* bv_dec     = (const float*)d_in[23];
    const float* wq_final   = (const float*)d_in[24];
    const float* wk_final   = (const float*)d_in[25];
    float* out = (float*)d_out;

    float* base = nullptr;
    cudaGetSymbolAddress((void**)&base, g_scratch);
    float* ph    = base;
    float* pt    = base + OFF_T;
    float* pQ    = base + OFF_Q;
    float* pf    = base + OFF_F;
    float* pKatt = base + OFF_KATT;
    float* pVatt = base + OFF_VATT;
    float* pKfin = base + OFF_KFIN;
    float* ppart = base + OFF_PART;
    float* pmean = base + OFF_MEAN;
    float* prstd = base + OFF_RSTD;
    float* ppe   = base + OFF_PE;
    float* pKc   = base + OFF_KC;
    float* pVc   = base + OFF_VC;

    embed_kernel<<<(MTOT * DIM + 255) / 256, 256>>>(x, w_input, b_input, start_ph, ph);
    pe_kernel<<<(NNOD * DIM + 255) / 256, 256>>>(ppe);

    dim3 gDD(DIM / 64, MTOT / 64);            // N=128
    dim3 gQKV(DIM / 64, MTOT / 64, 3);        // fused Q,K,V
    dim3 gDF(FFD / 64, MTOT / 64);            // N=512
    dim3 gD2(256 / 64, MTOT / 64);            // N=256

    for (int l = 0; l < NLE; l++) {
        const float* aw = enc_attn_w + (size_t)l * 4 * DIM * DIM;
        const float* ab = enc_attn_b + (size_t)l * 4 * DIM;
        sgemm<true, false, false, true><<<gQKV, 256>>>(ph, aw, ab, nullptr, pQ, MTOT, DIM, DIM);
        enc_attn<<<BB * NH, 128>>>(pQ, pQ + SZ_MD, pQ + 2 * SZ_MD, base + OFF_O);
        sgemm<true, false, true, false><<<gDD, 256>>>(base + OFF_O, aw + 3 * DIM * DIM,
                 ab + 3 * DIM, ph, pt, MTOT, DIM, DIM);
        bn_partial<<<64, 256>>>(pt, ppart);
        bn_reduce<<<1, 128>>>(ppart, pmean, prstd);
        bn_apply<<<(MTOT * DIM + 255) / 256, 256>>>(pt, pmean, prstd,
                 enc_bn + ((l * 2 + 0) * 2 + 0) * DIM, enc_bn + ((l * 2 + 0) * 2 + 1) * DIM, ph);
        sgemm<true, true, false, false><<<gDF, 256>>>(ph, enc_ffn_w1 + (size_t)l * DIM * FFD,
                 enc_ffn_b1 + (size_t)l * FFD, nullptr, pf, MTOT, FFD, DIM);
        sgemm<true, false, true, false><<<gDD, 256>>>(pf, enc_ffn_w2 + (size_t)l * FFD * DIM,
                 enc_ffn_b2 + (size_t)l * DIM, ph, pt, MTOT, DIM, FFD);
        bn_partial<<<64, 256>>>(pt, ppart);
        bn_reduce<<<1, 128>>>(ppart, pmean, prstd);
        bn_apply<<<(MTOT * DIM + 255) / 256, 256>>>(pt, pmean, prstd,
                 enc_bn + ((l * 2 + 1) * 2 + 0) * DIM, enc_bn + ((l * 2 + 1) * 2 + 1) * DIM, ph);
    }

    sgemm<true,  false, false, false><<<gD2, 256>>>(ph, wk_dec,   bk_dec,  nullptr, pKatt, MTOT, NLD * DIM, DIM);
    sgemm<true,  false, false, false><<<gD2, 256>>>(ph, wv_dec,   bv_dec,  nullptr, pVatt, MTOT, NLD * DIM, DIM);
    sgemm<false, false, false, false><<<gDD, 256>>>(ph, wk_final, nullptr, nullptr, pKfin, MTOT, DIM, DIM);

    decoder_kernel<<<BB, 512>>>(ph, ppe, pKatt, pVatt, pKfin, pKc, pVc,
                                dec_self_w, dec_self_b, dec_cross_w, dec_cross_b,
                                dec_ffn_w1, dec_ffn_b1, dec_ffn_w2, dec_ffn_b2,
                                dec_ln, wq_final, out);
}